// round 3
// baseline (speedup 1.0000x reference)
#include <cuda_runtime.h>
#include <cstdint>

// GruLayer: B=64, T=512, D_in=L=1024.
// Phase A (parallel): XG[t*64+b, 0:2048] = x[b,t] @ w_W[0:1024,:] + w_b
//                     XG[t*64+b, 2048:3072] = x[b,t] @ wx_W + wx_b
// Phase B (sequential, 512 kernels): per t,
//   G = h_{t-1} @ [w_W[1024:,:] | wh_W]   (64 x 3072, tf32 mma)
//   hs = sigmoid(G[:, :1024] + XG[t,:, :1024])
//   os = sigmoid(G[:,1024:2048] + XG[t,:,1024:2048])
//   m  = XG[t,:,2048:] + hs * (G[:,2048:] + wh_b)
//   h_t = os*h + (1-os)*tanh(m)  -> written to out[:, t, :]
// h history lives in `out` itself (step t reads out[:, t-1, :]).

__device__ float g_XG[(size_t)32768 * 3072];   // [t*64+b][3072] scratch (~403 MB)

__device__ __forceinline__ uint32_t f2tf(float x) {
    uint32_t r;
    asm("cvt.rna.tf32.f32 %0, %1;" : "=r"(r) : "f"(x));
    return r;
}

__device__ __forceinline__ void mma8(float* c,
                                     uint32_t a0, uint32_t a1, uint32_t a2, uint32_t a3,
                                     uint32_t b0, uint32_t b1) {
    asm volatile(
        "mma.sync.aligned.m16n8k8.row.col.f32.tf32.tf32.f32 "
        "{%0,%1,%2,%3},{%4,%5,%6,%7},{%8,%9},{%0,%1,%2,%3};"
        : "+f"(c[0]), "+f"(c[1]), "+f"(c[2]), "+f"(c[3])
        : "r"(a0), "r"(a1), "r"(a2), "r"(a3), "r"(b0), "r"(b1));
}

// ---------------------------------------------------------------------------
// Phase A: C[32768,3072] = X[32768,1024] @ [w_W_top | wx_W] + bias
// Block tile 64x64, k-tile 32, 8 warps (warp tile 16x32). Output rows permuted
// to [t][b] order.
// ---------------------------------------------------------------------------
__global__ __launch_bounds__(256) void phaseA_kernel(
    const float* __restrict__ X,
    const float* __restrict__ wW,    // [2048,2048]
    const float* __restrict__ wb,    // [2048]
    const float* __restrict__ wxW,   // [1024,1024]
    const float* __restrict__ wxb)   // [1024]
{
    __shared__ uint32_t As[64][36];
    __shared__ uint32_t Bs[32][68];

    const int tid  = threadIdx.x;
    const int warp = tid >> 5, lane = tid & 31;
    const int gID  = lane >> 2, tig = lane & 3;
    const int wm   = warp & 3, wn = warp >> 2;
    const int row0 = blockIdx.y * 64;
    const int j0   = blockIdx.x * 64;

    const float* Bsrc;
    int ws;
    if (j0 < 2048) { Bsrc = wW + j0;          ws = 2048; }
    else           { Bsrc = wxW + (j0 - 2048); ws = 1024; }

    float acc[4][4];
#pragma unroll
    for (int i = 0; i < 4; i++)
#pragma unroll
        for (int j = 0; j < 4; j++) acc[i][j] = 0.f;

    for (int kt = 0; kt < 1024; kt += 32) {
        // A tile 64x32 -> 512 float4 loads across 256 threads
#pragma unroll
        for (int i = 0; i < 2; i++) {
            int idx = tid + i * 256;
            int r = idx >> 3, c = (idx & 7) << 2;
            float4 v = *reinterpret_cast<const float4*>(
                X + (size_t)(row0 + r) * 1024 + kt + c);
            As[r][c + 0] = f2tf(v.x); As[r][c + 1] = f2tf(v.y);
            As[r][c + 2] = f2tf(v.z); As[r][c + 3] = f2tf(v.w);
        }
        // B tile 32x64 -> 512 float4
#pragma unroll
        for (int i = 0; i < 2; i++) {
            int idx = tid + i * 256;
            int r = idx >> 4, c = (idx & 15) << 2;
            float4 v = *reinterpret_cast<const float4*>(
                Bsrc + (size_t)(kt + r) * ws + c);
            Bs[r][c + 0] = f2tf(v.x); Bs[r][c + 1] = f2tf(v.y);
            Bs[r][c + 2] = f2tf(v.z); Bs[r][c + 3] = f2tf(v.w);
        }
        __syncthreads();

#pragma unroll
        for (int ks = 0; ks < 4; ks++) {
            int k0 = ks * 8, m0 = wm * 16;
            uint32_t a0 = As[m0 + gID][k0 + tig];
            uint32_t a1 = As[m0 + gID + 8][k0 + tig];
            uint32_t a2 = As[m0 + gID][k0 + tig + 4];
            uint32_t a3 = As[m0 + gID + 8][k0 + tig + 4];
#pragma unroll
            for (int nf = 0; nf < 4; nf++) {
                int n0 = wn * 32 + nf * 8;
                uint32_t b0 = Bs[k0 + tig][n0 + gID];
                uint32_t b1 = Bs[k0 + tig + 4][n0 + gID];
                mma8(acc[nf], a0, a1, a2, a3, b0, b1);
            }
        }
        __syncthreads();
    }

#pragma unroll
    for (int nf = 0; nf < 4; nf++) {
        int col = j0 + wn * 32 + nf * 8 + tig * 2;
        float b0v, b1v;
        if (col < 2048) { b0v = wb[col];        b1v = wb[col + 1]; }
        else            { b0v = wxb[col - 2048]; b1v = wxb[col - 2047]; }
#pragma unroll
        for (int h = 0; h < 2; h++) {
            int grow = row0 + wm * 16 + gID + h * 8;   // row in (b*512 + t) order
            int bb = grow >> 9, tt = grow & 511;
            size_t orow = (size_t)(tt * 64 + bb) * 3072;
            g_XG[orow + col]     = acc[nf][h * 2]     + b0v;
            g_XG[orow + col + 1] = acc[nf][h * 2 + 1] + b1v;
        }
    }
}

// ---------------------------------------------------------------------------
// Phase B: one kernel per time step. 128 blocks x 128 threads.
// Block = 8-column tile of the latent dim; computes the matching 8-col tiles
// of all three recurrent weight groups, then the fused nonlinearity.
// ---------------------------------------------------------------------------
__global__ __launch_bounds__(128) void step_kernel(
    int t,
    const float* __restrict__ hprev, int hstride,
    const float* __restrict__ wW,     // [2048,2048]
    const float* __restrict__ whW,    // [1024,1024]
    const float* __restrict__ whb,    // [1024]
    float* __restrict__ out)          // [64,512,1024]
{
    __shared__ uint32_t Hs[64][36];
    __shared__ uint32_t Ws[3][32][8];

    const int tid  = threadIdx.x;
    const int warp = tid >> 5, lane = tid & 31;
    const int gID  = lane >> 2, tig = lane & 3;
    const int jt   = blockIdx.x * 8;

    float acc[3][4];
#pragma unroll
    for (int g = 0; g < 3; g++)
#pragma unroll
        for (int i = 0; i < 4; i++) acc[g][i] = 0.f;

    for (int kt = 0; kt < 1024; kt += 32) {
        // H tile 64x32 -> 512 float4 across 128 threads
#pragma unroll
        for (int i = 0; i < 4; i++) {
            int idx = tid + i * 128;
            int r = idx >> 3, c = (idx & 7) << 2;
            float4 v = *reinterpret_cast<const float4*>(
                hprev + (size_t)r * hstride + kt + c);
            Hs[r][c + 0] = f2tf(v.x); Hs[r][c + 1] = f2tf(v.y);
            Hs[r][c + 2] = f2tf(v.z); Hs[r][c + 3] = f2tf(v.w);
        }
        // Weight tiles: 3 groups x 32 x 8 = 768 scalars
#pragma unroll
        for (int i = 0; i < 6; i++) {
            int idx = tid + i * 128;
            int g = idx >> 8, r2 = idx & 255, kr = r2 >> 3, c = r2 & 7;
            float v;
            if (g == 0)      v = wW[(size_t)(1024 + kt + kr) * 2048 + jt + c];
            else if (g == 1) v = wW[(size_t)(1024 + kt + kr) * 2048 + 1024 + jt + c];
            else             v = whW[(size_t)(kt + kr) * 1024 + jt + c];
            Ws[g][kr][c] = f2tf(v);
        }
        __syncthreads();

#pragma unroll
        for (int ks = 0; ks < 4; ks++) {
            int k0 = ks * 8, m0 = warp * 16;
            uint32_t a0 = Hs[m0 + gID][k0 + tig];
            uint32_t a1 = Hs[m0 + gID + 8][k0 + tig];
            uint32_t a2 = Hs[m0 + gID][k0 + tig + 4];
            uint32_t a3 = Hs[m0 + gID + 8][k0 + tig + 4];
#pragma unroll
            for (int g = 0; g < 3; g++) {
                uint32_t b0 = Ws[g][k0 + tig][gID];
                uint32_t b1 = Ws[g][k0 + tig + 4][gID];
                mma8(acc[g], a0, a1, a2, a3, b0, b1);
            }
        }
        __syncthreads();
    }

    // Fused combine + write h_t
#pragma unroll
    for (int h = 0; h < 2; h++) {
        int r = warp * 16 + gID + h * 8;           // batch index
        size_t xbase = ((size_t)t * 64 + r) * 3072;
#pragma unroll
        for (int cc = 0; cc < 2; cc++) {
            int j = jt + tig * 2 + cc;
            float g1 = acc[0][h * 2 + cc] + g_XG[xbase + j];
            float g2 = acc[1][h * 2 + cc] + g_XG[xbase + 1024 + j];
            float hm = acc[2][h * 2 + cc] + whb[j];
            float xm = g_XG[xbase + 2048 + j];
            float hs = 1.f / (1.f + __expf(-g1));
            float os = 1.f / (1.f + __expf(-g2));
            float m  = xm + hs * hm;
            float hp = hprev[(size_t)r * hstride + j];
            float hn = os * hp + (1.f - os) * tanhf(m);
            out[((size_t)r * 512 + t) * 1024 + j] = hn;
        }
    }
}

extern "C" void kernel_launch(void* const* d_in, const int* in_sizes, int n_in,
                              void* d_out, int out_size) {
    const float* x   = (const float*)d_in[0];
    const float* h0  = (const float*)d_in[1];
    const float* wW  = (const float*)d_in[2];
    const float* wb  = (const float*)d_in[3];
    const float* wxW = (const float*)d_in[4];
    const float* wxb = (const float*)d_in[5];
    const float* whW = (const float*)d_in[6];
    const float* whb = (const float*)d_in[7];
    float* out = (float*)d_out;

    // Phase A: 48 n-tiles x 512 m-tiles
    phaseA_kernel<<<dim3(48, 512), 256>>>(x, wW, wb, wxW, wxb);

    // Phase B: 512 sequential steps
    for (int t = 0; t < 512; t++) {
        const float* hp = (t == 0) ? h0 : (out + (size_t)(t - 1) * 1024);
        int hstride = (t == 0) ? 1024 : 512 * 1024;
        step_kernel<<<128, 128>>>(t, hp, hstride, wW, whW, whb, out);
    }
}

// round 4
// speedup vs baseline: 2.5441x; 2.5441x over previous
#include <cuda_runtime.h>
#include <cuda_fp16.h>
#include <cstdint>

// GruLayer: B=64, T=512, D_in=L=1024.
// Phase A (parallel GEMM, tf32): XG[t*64+b, 0:2048]  = x[b,t] @ w_W[0:1024,:] + w_b
//                                XG[t*64+b, 2048:3072] = x[b,t] @ wx_W + wx_b
// Phase B (persistent kernel, 512 steps, fp16 MMA):
//   G = h_{t-1} @ [w_W[1024:,:] | wh_W]
//   hs = sigmoid(G1+XG1); os = sigmoid(G2+XG2)
//   h_t = os*h + (1-os)*tanh(XGm + hs*(Gm + wh_b))
// Weights live in smem (fp16) for the whole kernel; h ping-pongs through a
// fp16 __device__ buffer; fp32 h history lives in `out`.

__device__ float g_XG[(size_t)32768 * 3072];     // [t*64+b][3072] scratch (~403 MB)
__device__ __half g_h[2 * 64 * 1024];            // fp16 h ping-pong
__device__ unsigned g_arrive;                    // grid barrier counter

__device__ __forceinline__ uint32_t f2tf(float x) {
    uint32_t r;
    asm("cvt.rna.tf32.f32 %0, %1;" : "=r"(r) : "f"(x));
    return r;
}

__device__ __forceinline__ void mma_tf32(float* c,
                                         uint32_t a0, uint32_t a1, uint32_t a2, uint32_t a3,
                                         uint32_t b0, uint32_t b1) {
    asm volatile(
        "mma.sync.aligned.m16n8k8.row.col.f32.tf32.tf32.f32 "
        "{%0,%1,%2,%3},{%4,%5,%6,%7},{%8,%9},{%0,%1,%2,%3};"
        : "+f"(c[0]), "+f"(c[1]), "+f"(c[2]), "+f"(c[3])
        : "r"(a0), "r"(a1), "r"(a2), "r"(a3), "r"(b0), "r"(b1));
}

__device__ __forceinline__ void mma_f16(float* c,
                                        uint32_t a0, uint32_t a1, uint32_t a2, uint32_t a3,
                                        uint32_t b0, uint32_t b1) {
    asm volatile(
        "mma.sync.aligned.m16n8k16.row.col.f32.f16.f16.f32 "
        "{%0,%1,%2,%3},{%4,%5,%6,%7},{%8,%9},{%0,%1,%2,%3};"
        : "+f"(c[0]), "+f"(c[1]), "+f"(c[2]), "+f"(c[3])
        : "r"(a0), "r"(a1), "r"(a2), "r"(a3), "r"(b0), "r"(b1));
}

// ---------------------------------------------------------------------------
// Phase A (unchanged from R2): C[32768,3072] = X @ [w_W_top | wx_W] + bias
// ---------------------------------------------------------------------------
__global__ __launch_bounds__(256) void phaseA_kernel(
    const float* __restrict__ X,
    const float* __restrict__ wW,    // [2048,2048]
    const float* __restrict__ wb,    // [2048]
    const float* __restrict__ wxW,   // [1024,1024]
    const float* __restrict__ wxb)   // [1024]
{
    __shared__ uint32_t As[64][36];
    __shared__ uint32_t Bs[32][68];

    const int tid  = threadIdx.x;
    const int warp = tid >> 5, lane = tid & 31;
    const int gID  = lane >> 2, tig = lane & 3;
    const int wm   = warp & 3, wn = warp >> 2;
    const int row0 = blockIdx.y * 64;
    const int j0   = blockIdx.x * 64;

    const float* Bsrc;
    int ws;
    if (j0 < 2048) { Bsrc = wW + j0;          ws = 2048; }
    else           { Bsrc = wxW + (j0 - 2048); ws = 1024; }

    float acc[4][4];
#pragma unroll
    for (int i = 0; i < 4; i++)
#pragma unroll
        for (int j = 0; j < 4; j++) acc[i][j] = 0.f;

    for (int kt = 0; kt < 1024; kt += 32) {
#pragma unroll
        for (int i = 0; i < 2; i++) {
            int idx = tid + i * 256;
            int r = idx >> 3, c = (idx & 7) << 2;
            float4 v = *reinterpret_cast<const float4*>(
                X + (size_t)(row0 + r) * 1024 + kt + c);
            As[r][c + 0] = f2tf(v.x); As[r][c + 1] = f2tf(v.y);
            As[r][c + 2] = f2tf(v.z); As[r][c + 3] = f2tf(v.w);
        }
#pragma unroll
        for (int i = 0; i < 2; i++) {
            int idx = tid + i * 256;
            int r = idx >> 4, c = (idx & 15) << 2;
            float4 v = *reinterpret_cast<const float4*>(
                Bsrc + (size_t)(kt + r) * ws + c);
            Bs[r][c + 0] = f2tf(v.x); Bs[r][c + 1] = f2tf(v.y);
            Bs[r][c + 2] = f2tf(v.z); Bs[r][c + 3] = f2tf(v.w);
        }
        __syncthreads();

#pragma unroll
        for (int ks = 0; ks < 4; ks++) {
            int k0 = ks * 8, m0 = wm * 16;
            uint32_t a0 = As[m0 + gID][k0 + tig];
            uint32_t a1 = As[m0 + gID + 8][k0 + tig];
            uint32_t a2 = As[m0 + gID][k0 + tig + 4];
            uint32_t a3 = As[m0 + gID + 8][k0 + tig + 4];
#pragma unroll
            for (int nf = 0; nf < 4; nf++) {
                int n0 = wn * 32 + nf * 8;
                uint32_t b0 = Bs[k0 + tig][n0 + gID];
                uint32_t b1 = Bs[k0 + tig + 4][n0 + gID];
                mma_tf32(acc[nf], a0, a1, a2, a3, b0, b1);
            }
        }
        __syncthreads();
    }

#pragma unroll
    for (int nf = 0; nf < 4; nf++) {
        int col = j0 + wn * 32 + nf * 8 + tig * 2;
        float b0v, b1v;
        if (col < 2048) { b0v = wb[col];        b1v = wb[col + 1]; }
        else            { b0v = wxb[col - 2048]; b1v = wxb[col - 2047]; }
#pragma unroll
        for (int h = 0; h < 2; h++) {
            int grow = row0 + wm * 16 + gID + h * 8;   // row in (b*512 + t) order
            int bb = grow >> 9, tt = grow & 511;
            size_t orow = (size_t)(tt * 64 + bb) * 3072;
            g_XG[orow + col]     = acc[nf][h * 2]     + b0v;
            g_XG[orow + col + 1] = acc[nf][h * 2 + 1] + b1v;
        }
    }
}

// ---------------------------------------------------------------------------
// Init: h0 -> fp16 ping buffer 0, reset grid-barrier counter.
// ---------------------------------------------------------------------------
__global__ void initB_kernel(const float* __restrict__ h0) {
    int i = blockIdx.x * 256 + threadIdx.x;   // 65536 threads
    g_h[i] = __float2half_rn(h0[i]);
    if (i == 0) g_arrive = 0;
}

// ---------------------------------------------------------------------------
// Phase B: persistent kernel. 128 blocks x 128 threads, all co-resident.
// Block = 8-column tile of latent dim; weights (3 groups) cached in smem fp16.
// Per step: stage h (fp16, L2 broadcast) -> smem, 3 fused GEMV-tiles via
// m16n8k16 HMMA, fused nonlinearity, write fp32 out + fp16 h_next, grid sync.
// ---------------------------------------------------------------------------
#define SMEM_W_STRIDE 1032   // halves per weight column (pad 8 -> conflict-free)
#define SMEM_H_STRIDE 1032   // halves per h row

__global__ __launch_bounds__(128) void phaseB_kernel(
    const float* __restrict__ h0,
    const float* __restrict__ wW,     // [2048,2048]
    const float* __restrict__ whW,    // [1024,1024]
    const float* __restrict__ whb,    // [1024]
    float* __restrict__ out)          // [64,512,1024]
{
    extern __shared__ __align__(16) __half smem[];
    __half* Wt = smem;                               // [3*8][1032]
    __half* Hs = smem + 3 * 8 * SMEM_W_STRIDE;       // [64][1032]

    const int tid  = threadIdx.x;
    const int warp = tid >> 5, lane = tid & 31;
    const int gID  = lane >> 2, tig = lane & 3;
    const int jt   = blockIdx.x * 8;
    const int m0   = warp * 16;
    const int jcol0 = jt + tig * 2;

    // ---- one-time: load + transpose weights into smem as fp16 [group*8+col][k]
    for (int idx = tid; idx < 3 * 8 * 1024; idx += 128) {
        int col = idx & 7;
        int k   = (idx >> 3) & 1023;
        int g   = idx >> 13;
        float v;
        if (g == 0)      v = wW[(size_t)(1024 + k) * 2048 + jt + col];
        else if (g == 1) v = wW[(size_t)(1024 + k) * 2048 + 1024 + jt + col];
        else             v = whW[(size_t)k * 1024 + jt + col];
        Wt[(g * 8 + col) * SMEM_W_STRIDE + k] = __float2half_rn(v);
    }
    const float bwh0 = whb[jcol0];
    const float bwh1 = whb[jcol0 + 1];
    __syncthreads();

    // per-thread smem base pointers
    const __half* pa_lo = Hs + (m0 + gID) * SMEM_H_STRIDE + tig * 2;
    const __half* pa_hi = Hs + (m0 + gID + 8) * SMEM_H_STRIDE + tig * 2;
    const __half* pb0 = Wt + (0 * 8 + gID) * SMEM_W_STRIDE + tig * 2;
    const __half* pb1 = Wt + (1 * 8 + gID) * SMEM_W_STRIDE + tig * 2;
    const __half* pb2 = Wt + (2 * 8 + gID) * SMEM_W_STRIDE + tig * 2;

    for (int t = 0; t < 512; t++) {
        const __half* hsrc = g_h + (size_t)(t & 1) * 65536;
        __half*       hdst = g_h + (size_t)((t + 1) & 1) * 65536;

        // ---- prefetch epilogue operands (XG slice + fp32 h_prev) into regs
        float xg[2][2][3], hpv[2][2];
        {
            size_t xb = (size_t)t * 64 * 3072;
#pragma unroll
            for (int h = 0; h < 2; h++) {
                int r = m0 + gID + h * 8;
                const float* xr = g_XG + xb + (size_t)r * 3072 + jcol0;
#pragma unroll
                for (int cc = 0; cc < 2; cc++) {
                    xg[h][cc][0] = xr[cc];
                    xg[h][cc][1] = xr[1024 + cc];
                    xg[h][cc][2] = xr[2048 + cc];
                    hpv[h][cc] = (t == 0)
                        ? h0[(size_t)r * 1024 + jcol0 + cc]
                        : out[((size_t)r * 512 + (t - 1)) * 1024 + jcol0 + cc];
                }
            }
        }

        // ---- stage h (fp16) into smem; L2-only loads (other SMs wrote it)
#pragma unroll 4
        for (int i = tid; i < 8192; i += 128) {
            int r = i >> 7, c = i & 127;            // 8-half chunks
            uint4 v = __ldcg((const uint4*)(hsrc + (size_t)r * 1024 + c * 8));
            *(uint4*)(Hs + (size_t)r * SMEM_H_STRIDE + c * 8) = v;
        }
        __syncthreads();

        // ---- 3 fused 64x8 GEMM tiles over k=1024
        float acc[3][4];
#pragma unroll
        for (int g = 0; g < 3; g++)
#pragma unroll
            for (int i = 0; i < 4; i++) acc[g][i] = 0.f;

#pragma unroll 8
        for (int k0 = 0; k0 < 1024; k0 += 16) {
            uint32_t a0 = *(const uint32_t*)(pa_lo + k0);
            uint32_t a1 = *(const uint32_t*)(pa_hi + k0);
            uint32_t a2 = *(const uint32_t*)(pa_lo + k0 + 8);
            uint32_t a3 = *(const uint32_t*)(pa_hi + k0 + 8);
            {
                uint32_t b0 = *(const uint32_t*)(pb0 + k0);
                uint32_t b1 = *(const uint32_t*)(pb0 + k0 + 8);
                mma_f16(acc[0], a0, a1, a2, a3, b0, b1);
            }
            {
                uint32_t b0 = *(const uint32_t*)(pb1 + k0);
                uint32_t b1 = *(const uint32_t*)(pb1 + k0 + 8);
                mma_f16(acc[1], a0, a1, a2, a3, b0, b1);
            }
            {
                uint32_t b0 = *(const uint32_t*)(pb2 + k0);
                uint32_t b1 = *(const uint32_t*)(pb2 + k0 + 8);
                mma_f16(acc[2], a0, a1, a2, a3, b0, b1);
            }
        }

        // ---- fused nonlinearity + stores
#pragma unroll
        for (int h = 0; h < 2; h++) {
            int r = m0 + gID + h * 8;
            float hn[2];
#pragma unroll
            for (int cc = 0; cc < 2; cc++) {
                float g1 = acc[0][h * 2 + cc] + xg[h][cc][0];
                float g2 = acc[1][h * 2 + cc] + xg[h][cc][1];
                float hm = acc[2][h * 2 + cc] + ((cc == 0) ? bwh0 : bwh1);
                float xm = xg[h][cc][2];
                float hs = 1.f / (1.f + __expf(-g1));
                float os = 1.f / (1.f + __expf(-g2));
                float mm = xm + hs * hm;
                hn[cc] = os * hpv[h][cc] + (1.f - os) * tanhf(mm);
                out[((size_t)r * 512 + t) * 1024 + jcol0 + cc] = hn[cc];
            }
            *(reinterpret_cast<__half2*>(hdst + (size_t)r * 1024 + jcol0)) =
                __floats2half2_rn(hn[0], hn[1]);
        }

        // ---- grid barrier (release h writes, wait for all 128 blocks)
        __threadfence();
        __syncthreads();
        if (tid == 0) {
            atomicAdd(&g_arrive, 1u);
            unsigned target = (unsigned)(t + 1) * 128u;
            unsigned v;
            do {
                asm volatile("ld.global.acquire.gpu.u32 %0, [%1];"
                             : "=r"(v) : "l"(&g_arrive));
            } while (v < target);
        }
        __syncthreads();
    }
}

extern "C" void kernel_launch(void* const* d_in, const int* in_sizes, int n_in,
                              void* d_out, int out_size) {
    const float* x   = (const float*)d_in[0];
    const float* h0  = (const float*)d_in[1];
    const float* wW  = (const float*)d_in[2];
    const float* wb  = (const float*)d_in[3];
    const float* wxW = (const float*)d_in[4];
    const float* wxb = (const float*)d_in[5];
    const float* whW = (const float*)d_in[6];
    const float* whb = (const float*)d_in[7];
    float* out = (float*)d_out;

    // Phase B needs ~181 KB dynamic smem
    const int smemB = (3 * 8 * SMEM_W_STRIDE + 64 * SMEM_H_STRIDE) * (int)sizeof(__half);
    cudaFuncSetAttribute(phaseB_kernel,
                         cudaFuncAttributeMaxDynamicSharedMemorySize, smemB);

    initB_kernel<<<256, 256>>>(h0);
    phaseA_kernel<<<dim3(48, 512), 256>>>(x, wW, wb, wxW, wxb);
    phaseB_kernel<<<128, 128, smemB>>>(h0, wW, whW, whb, out);
}

// round 5
// speedup vs baseline: 3.1830x; 1.2511x over previous
#include <cuda_runtime.h>
#include <cuda_fp16.h>
#include <cstdint>

// GruLayer: B=64, T=512, D_in=L=1024.
// Prep: X -> fp16 g_Xh; weights -> fp16 transposed g_Bt (x-proj) / g_Br (recurrent).
// Phase A (fp16 HMMA GEMM): XG[t*64+b, 0:3072] = x @ [w_W_top | wx_W] + bias
// Phase B (persistent, 512 steps, fp16 HMMA):
//   G = h_{t-1} @ [w_W_bot | wh_W];  hs=sig(G1+XG1); os=sig(G2+XG2)
//   h_t = os*h + (1-os)*tanh(XGm + hs*(Gm + wh_b))

__device__ float  g_XG[(size_t)32768 * 3072];   // [t*64+b][3072] scratch (~403 MB)
__device__ __half g_Xh[(size_t)32768 * 1024];   // X fp16 (64 MB, L2-resident)
__device__ __half g_Bt[(size_t)3072 * 1024];    // [n][k] fp16: n<2048: wW[k][n]; else wxW[k][n-2048]
__device__ __half g_Br[(size_t)3072 * 1024];    // [n][k] fp16: n<2048: wW[1024+k][n]; else whW[k][n-2048]
__device__ __half g_h[2 * 64 * 1024];           // fp16 h ping-pong
__device__ unsigned g_arrive;                   // grid barrier counter

__device__ __forceinline__ void mma_f16(float* c,
                                        uint32_t a0, uint32_t a1, uint32_t a2, uint32_t a3,
                                        uint32_t b0, uint32_t b1) {
    asm volatile(
        "mma.sync.aligned.m16n8k16.row.col.f32.f16.f16.f32 "
        "{%0,%1,%2,%3},{%4,%5,%6,%7},{%8,%9},{%0,%1,%2,%3};"
        : "+f"(c[0]), "+f"(c[1]), "+f"(c[2]), "+f"(c[3])
        : "r"(a0), "r"(a1), "r"(a2), "r"(a3), "r"(b0), "r"(b1));
}

__device__ __forceinline__ void cp_async16(void* smem, const void* gmem) {
    uint32_t s = (uint32_t)__cvta_generic_to_shared(smem);
    asm volatile("cp.async.cg.shared.global [%0], [%1], 16;" :: "r"(s), "l"(gmem));
}
__device__ __forceinline__ void cp_commit() {
    asm volatile("cp.async.commit_group;");
}
template <int N>
__device__ __forceinline__ void cp_wait() {
    asm volatile("cp.async.wait_group %0;" :: "n"(N));
}

// ---------------------------------------------------------------------------
// Prep 1: X fp32 -> fp16 (each thread 8 elements)
// ---------------------------------------------------------------------------
__global__ __launch_bounds__(256) void prep_x_kernel(const float* __restrict__ x) {
    size_t i = ((size_t)blockIdx.x * 256 + threadIdx.x) * 8;
    float4 v0 = *reinterpret_cast<const float4*>(x + i);
    float4 v1 = *reinterpret_cast<const float4*>(x + i + 4);
    __half2 h0 = __floats2half2_rn(v0.x, v0.y);
    __half2 h1 = __floats2half2_rn(v0.z, v0.w);
    __half2 h2 = __floats2half2_rn(v1.x, v1.y);
    __half2 h3 = __floats2half2_rn(v1.z, v1.w);
    uint4 o;
    o.x = *(uint32_t*)&h0; o.y = *(uint32_t*)&h1;
    o.z = *(uint32_t*)&h2; o.w = *(uint32_t*)&h3;
    *reinterpret_cast<uint4*>(g_Xh + i) = o;
}

// ---------------------------------------------------------------------------
// Prep 2: weights -> fp16, transposed to [n][k]. z=0 -> g_Bt, z=1 -> g_Br.
// ---------------------------------------------------------------------------
__global__ __launch_bounds__(256) void prep_w_kernel(
    const float* __restrict__ wW,    // [2048,2048]
    const float* __restrict__ wxW,   // [1024,1024]
    const float* __restrict__ whW)   // [1024,1024]
{
    __shared__ float tile[32][33];
    const int n0 = blockIdx.x * 32, k0 = blockIdx.y * 32;
    const int which = blockIdx.z;
    const int tx = threadIdx.x, ty = threadIdx.y;   // 32 x 8

    for (int i = ty; i < 32; i += 8) {
        int k = k0 + i, n = n0 + tx;
        float v;
        if (which == 0) v = (n < 2048) ? wW[(size_t)k * 2048 + n]
                                       : wxW[(size_t)k * 1024 + (n - 2048)];
        else            v = (n < 2048) ? wW[(size_t)(1024 + k) * 2048 + n]
                                       : whW[(size_t)k * 1024 + (n - 2048)];
        tile[i][tx] = v;
    }
    __syncthreads();
    __half* dst = which ? g_Br : g_Bt;
    for (int i = ty; i < 32; i += 8) {
        int n = n0 + i, k = k0 + tx;
        dst[(size_t)n * 1024 + k] = __float2half_rn(tile[tx][i]);
    }
}

// ---------------------------------------------------------------------------
// Init: h0 -> fp16 ping buffer 0, reset grid-barrier counter.
// ---------------------------------------------------------------------------
__global__ void initB_kernel(const float* __restrict__ h0) {
    int i = blockIdx.x * 256 + threadIdx.x;   // 65536 threads
    g_h[i] = __float2half_rn(h0[i]);
    if (i == 0) g_arrive = 0;
}

// ---------------------------------------------------------------------------
// Phase A: C[32768,3072] = Xh @ Bt^T + bias, fp16 HMMA.
// Block tile 128x128, k-step 32, double-buffered cp.async.
// 8 warps: wm = warp>>2 (2 m-halves of 64), wn = warp&3 (4 n-strips of 32).
// Smem word-stride 20 (40 halves) -> conflict-free fragment LDS.
// Output rows permuted to [t][b] order, written fp32 to g_XG.
// ---------------------------------------------------------------------------
#define PA_STRIDE_W 20   // 32-bit words per smem row (32 halves + pad)

__global__ __launch_bounds__(256) void phaseA_kernel(
    const float* __restrict__ wb,    // [2048]
    const float* __restrict__ wxb)   // [1024]
{
    __shared__ __align__(16) __half Ah[2][128 * PA_STRIDE_W * 2];
    __shared__ __align__(16) __half Bh[2][128 * PA_STRIDE_W * 2];

    const int tid  = threadIdx.x;
    const int warp = tid >> 5, lane = tid & 31;
    const int gID  = lane >> 2, tig = lane & 3;
    const int wm   = warp >> 2, wn = warp & 3;
    const int row0 = blockIdx.y * 128;
    const int j0   = blockIdx.x * 128;

    // loader indices: 512 chunks of 16B per tile, 2 per thread
    const int lr0 = tid >> 1, lc0 = (tid & 1) << 1;  // rows 0..127, chunk pairs

    auto load_tile = [&](int buf, int kt) {
        // A: rows row0+r of g_Xh, 4 chunks/row
#pragma unroll
        for (int cc = 0; cc < 2; cc++) {
            int c = lc0 + cc;
            cp_async16(&Ah[buf][lr0 * (PA_STRIDE_W * 2) + c * 8],
                       g_Xh + (size_t)(row0 + lr0) * 1024 + kt + c * 8);
            cp_async16(&Bh[buf][lr0 * (PA_STRIDE_W * 2) + c * 8],
                       g_Bt + (size_t)(j0 + lr0) * 1024 + kt + c * 8);
        }
    };

    float acc[4][4][4];
#pragma unroll
    for (int mi = 0; mi < 4; mi++)
#pragma unroll
        for (int ni = 0; ni < 4; ni++)
#pragma unroll
            for (int i = 0; i < 4; i++) acc[mi][ni][i] = 0.f;

    load_tile(0, 0);
    cp_commit();

    const int m_base = wm * 64;
    const int n_base = wn * 32;

    for (int kt = 0; kt < 1024; kt += 32) {
        int buf = (kt >> 5) & 1;
        if (kt + 32 < 1024) load_tile(buf ^ 1, kt + 32);
        cp_commit();
        cp_wait<1>();
        __syncthreads();

        const uint32_t* Aw = reinterpret_cast<const uint32_t*>(Ah[buf]);
        const uint32_t* Bw = reinterpret_cast<const uint32_t*>(Bh[buf]);

#pragma unroll
        for (int ki = 0; ki < 2; ki++) {
            int wbase = ki * 8;
            uint32_t a[4][4];
#pragma unroll
            for (int mi = 0; mi < 4; mi++) {
                int r = m_base + mi * 16 + gID;
                a[mi][0] = Aw[r * PA_STRIDE_W + wbase + tig];
                a[mi][1] = Aw[(r + 8) * PA_STRIDE_W + wbase + tig];
                a[mi][2] = Aw[r * PA_STRIDE_W + wbase + tig + 4];
                a[mi][3] = Aw[(r + 8) * PA_STRIDE_W + wbase + tig + 4];
            }
#pragma unroll
            for (int ni = 0; ni < 4; ni++) {
                int n = n_base + ni * 8 + gID;
                uint32_t b0 = Bw[n * PA_STRIDE_W + wbase + tig];
                uint32_t b1 = Bw[n * PA_STRIDE_W + wbase + tig + 4];
#pragma unroll
                for (int mi = 0; mi < 4; mi++)
                    mma_f16(acc[mi][ni], a[mi][0], a[mi][1], a[mi][2], a[mi][3], b0, b1);
            }
        }
        __syncthreads();
    }

    // epilogue: bias + permuted fp32 store
    float bv[4][2];
#pragma unroll
    for (int ni = 0; ni < 4; ni++) {
        int col = j0 + n_base + ni * 8 + tig * 2;
        if (col < 2048) { bv[ni][0] = wb[col];         bv[ni][1] = wb[col + 1]; }
        else            { bv[ni][0] = wxb[col - 2048]; bv[ni][1] = wxb[col - 2047]; }
    }
#pragma unroll
    for (int mi = 0; mi < 4; mi++) {
#pragma unroll
        for (int h = 0; h < 2; h++) {
            int grow = row0 + m_base + mi * 16 + gID + h * 8;  // (b*512 + t)
            int bb = grow >> 9, tt = grow & 511;
            size_t orow = (size_t)(tt * 64 + bb) * 3072;
#pragma unroll
            for (int ni = 0; ni < 4; ni++) {
                int col = j0 + n_base + ni * 8 + tig * 2;
                g_XG[orow + col]     = acc[mi][ni][h * 2]     + bv[ni][0];
                g_XG[orow + col + 1] = acc[mi][ni][h * 2 + 1] + bv[ni][1];
            }
        }
    }
}

// ---------------------------------------------------------------------------
// Phase B: persistent kernel. 128 blocks x 128 threads, all co-resident.
// Block = 8-column tile of latent dim; weights cached in smem fp16 (from g_Br).
// ---------------------------------------------------------------------------
#define SMEM_W_STRIDE 1032   // halves per weight column (conflict-free)
#define SMEM_H_STRIDE 1032   // halves per h row

__global__ __launch_bounds__(128) void phaseB_kernel(
    const float* __restrict__ h0,
    const float* __restrict__ whb,    // [1024]
    float* __restrict__ out)          // [64,512,1024]
{
    extern __shared__ __align__(16) __half smem[];
    __half* Wt = smem;                               // [3*8][1032]
    __half* Hs = smem + 3 * 8 * SMEM_W_STRIDE;       // [64][1032]

    const int tid  = threadIdx.x;
    const int warp = tid >> 5, lane = tid & 31;
    const int gID  = lane >> 2, tig = lane & 3;
    const int jt   = blockIdx.x * 8;
    const int m0   = warp * 16;
    const int jcol0 = jt + tig * 2;

    // one-time: weights from g_Br (already [n][k] fp16) -> smem, 16B copies
    for (int idx = tid; idx < 3 * 8 * 128; idx += 128) {
        int row = idx >> 7, c = idx & 127;           // row = g*8+col, c = 8-half chunk
        int g = row >> 3, col = row & 7;
        uint4 v = *reinterpret_cast<const uint4*>(
            g_Br + (size_t)(g * 1024 + jt + col) * 1024 + c * 8);
        *reinterpret_cast<uint4*>(Wt + (size_t)row * SMEM_W_STRIDE + c * 8) = v;
    }
    const float bwh0 = whb[jcol0];
    const float bwh1 = whb[jcol0 + 1];
    __syncthreads();

    const __half* pa_lo = Hs + (m0 + gID) * SMEM_H_STRIDE + tig * 2;
    const __half* pa_hi = Hs + (m0 + gID + 8) * SMEM_H_STRIDE + tig * 2;
    const __half* pb0 = Wt + (0 * 8 + gID) * SMEM_W_STRIDE + tig * 2;
    const __half* pb1 = Wt + (1 * 8 + gID) * SMEM_W_STRIDE + tig * 2;
    const __half* pb2 = Wt + (2 * 8 + gID) * SMEM_W_STRIDE + tig * 2;

    for (int t = 0; t < 512; t++) {
        const __half* hsrc = g_h + (size_t)(t & 1) * 65536;
        __half*       hdst = g_h + (size_t)((t + 1) & 1) * 65536;

        // prefetch epilogue operands
        float xg[2][2][3], hpv[2][2];
        {
            size_t xb = (size_t)t * 64 * 3072;
#pragma unroll
            for (int h = 0; h < 2; h++) {
                int r = m0 + gID + h * 8;
                const float* xr = g_XG + xb + (size_t)r * 3072 + jcol0;
#pragma unroll
                for (int cc = 0; cc < 2; cc++) {
                    xg[h][cc][0] = xr[cc];
                    xg[h][cc][1] = xr[1024 + cc];
                    xg[h][cc][2] = xr[2048 + cc];
                    hpv[h][cc] = (t == 0)
                        ? h0[(size_t)r * 1024 + jcol0 + cc]
                        : out[((size_t)r * 512 + (t - 1)) * 1024 + jcol0 + cc];
                }
            }
        }

        // stage h (fp16) into smem; L2-only loads
#pragma unroll 4
        for (int i = tid; i < 8192; i += 128) {
            int r = i >> 7, c = i & 127;
            uint4 v = __ldcg((const uint4*)(hsrc + (size_t)r * 1024 + c * 8));
            *(uint4*)(Hs + (size_t)r * SMEM_H_STRIDE + c * 8) = v;
        }
        __syncthreads();

        float acc[3][4];
#pragma unroll
        for (int g = 0; g < 3; g++)
#pragma unroll
            for (int i = 0; i < 4; i++) acc[g][i] = 0.f;

#pragma unroll 8
        for (int k0 = 0; k0 < 1024; k0 += 16) {
            uint32_t a0 = *(const uint32_t*)(pa_lo + k0);
            uint32_t a1 = *(const uint32_t*)(pa_hi + k0);
            uint32_t a2 = *(const uint32_t*)(pa_lo + k0 + 8);
            uint32_t a3 = *(const uint32_t*)(pa_hi + k0 + 8);
            {
                uint32_t b0 = *(const uint32_t*)(pb0 + k0);
                uint32_t b1 = *(const uint32_t*)(pb0 + k0 + 8);
                mma_f16(acc[0], a0, a1, a2, a3, b0, b1);
            }
            {
                uint32_t b0 = *(const uint32_t*)(pb1 + k0);
                uint32_t b1 = *(const uint32_t*)(pb1 + k0 + 8);
                mma_f16(acc[1], a0, a1, a2, a3, b0, b1);
            }
            {
                uint32_t b0 = *(const uint32_t*)(pb2 + k0);
                uint32_t b1 = *(const uint32_t*)(pb2 + k0 + 8);
                mma_f16(acc[2], a0, a1, a2, a3, b0, b1);
            }
        }

        // fused nonlinearity + stores
#pragma unroll
        for (int h = 0; h < 2; h++) {
            int r = m0 + gID + h * 8;
            float hn[2];
#pragma unroll
            for (int cc = 0; cc < 2; cc++) {
                float g1 = acc[0][h * 2 + cc] + xg[h][cc][0];
                float g2 = acc[1][h * 2 + cc] + xg[h][cc][1];
                float hm = acc[2][h * 2 + cc] + ((cc == 0) ? bwh0 : bwh1);
                float xm = xg[h][cc][2];
                float hs = 1.f / (1.f + __expf(-g1));
                float os = 1.f / (1.f + __expf(-g2));
                float mm = xm + hs * hm;
                hn[cc] = os * hpv[h][cc] + (1.f - os) * tanhf(mm);
                out[((size_t)r * 512 + t) * 1024 + jcol0 + cc] = hn[cc];
            }
            *(reinterpret_cast<__half2*>(hdst + (size_t)r * 1024 + jcol0)) =
                __floats2half2_rn(hn[0], hn[1]);
        }

        // grid barrier
        __threadfence();
        __syncthreads();
        if (tid == 0) {
            atomicAdd(&g_arrive, 1u);
            unsigned target = (unsigned)(t + 1) * 128u;
            unsigned v;
            do {
                asm volatile("ld.global.acquire.gpu.u32 %0, [%1];"
                             : "=r"(v) : "l"(&g_arrive));
            } while (v < target);
        }
        __syncthreads();
    }
}

extern "C" void kernel_launch(void* const* d_in, const int* in_sizes, int n_in,
                              void* d_out, int out_size) {
    const float* x   = (const float*)d_in[0];
    const float* h0  = (const float*)d_in[1];
    const float* wW  = (const float*)d_in[2];
    const float* wb  = (const float*)d_in[3];
    const float* wxW = (const float*)d_in[4];
    const float* wxb = (const float*)d_in[5];
    const float* whW = (const float*)d_in[6];
    const float* whb = (const float*)d_in[7];
    float* out = (float*)d_out;

    const int smemB = (3 * 8 * SMEM_W_STRIDE + 64 * SMEM_H_STRIDE) * (int)sizeof(__half);
    cudaFuncSetAttribute(phaseB_kernel,
                         cudaFuncAttributeMaxDynamicSharedMemorySize, smemB);

    prep_x_kernel<<<16384, 256>>>(x);
    prep_w_kernel<<<dim3(96, 32, 2), dim3(32, 8)>>>(wW, wxW, whW);
    initB_kernel<<<256, 256>>>(h0);
    phaseA_kernel<<<dim3(24, 256), 256>>>(wb, wxb);
    phaseB_kernel<<<128, 128, smemB>>>(h0, whb, out);
}

// round 6
// speedup vs baseline: 4.7424x; 1.4899x over previous
#include <cuda_runtime.h>
#include <cuda_fp16.h>
#include <cstdint>

// GruLayer: B=64, T=512, D_in=L=1024.
// Prep: X -> fp16 g_Xh; weights -> fp16 transposed g_Bt (x-proj) / g_Br (recurrent).
// Phase A (fp16 HMMA, 3-stage cp.async): XG = x @ [w_W_top | wx_W] + bias
// Phase B (persistent, 512 steps, fp16 HMMA, k-split warps):
//   G = h_{t-1} @ [w_W_bot | wh_W];  hs=sig(G1+XG1); os=sig(G2+XG2)
//   h_t = os*h + (1-os)*tanh(XGm + hs*(Gm + wh_b))

__device__ float  g_XG[(size_t)32768 * 3072];   // [t*64+b][3072] scratch (~403 MB)
__device__ __half g_Xh[(size_t)32768 * 1024];   // X fp16 (64 MB)
__device__ __half g_Bt[(size_t)3072 * 1024];    // [n][k] fp16 x-proj weights
__device__ __half g_Br[(size_t)3072 * 1024];    // [n][k] fp16 recurrent weights
__device__ __half g_h[2 * 64 * 1024];           // fp16 h ping-pong
__device__ unsigned g_arrive;                   // grid barrier counter

__device__ __forceinline__ void mma_f16(float* c,
                                        uint32_t a0, uint32_t a1, uint32_t a2, uint32_t a3,
                                        uint32_t b0, uint32_t b1) {
    asm volatile(
        "mma.sync.aligned.m16n8k16.row.col.f32.f16.f16.f32 "
        "{%0,%1,%2,%3},{%4,%5,%6,%7},{%8,%9},{%0,%1,%2,%3};"
        : "+f"(c[0]), "+f"(c[1]), "+f"(c[2]), "+f"(c[3])
        : "r"(a0), "r"(a1), "r"(a2), "r"(a3), "r"(b0), "r"(b1));
}

__device__ __forceinline__ void cp_async16(void* smem, const void* gmem) {
    uint32_t s = (uint32_t)__cvta_generic_to_shared(smem);
    asm volatile("cp.async.cg.shared.global [%0], [%1], 16;" :: "r"(s), "l"(gmem));
}
__device__ __forceinline__ void cp_commit() {
    asm volatile("cp.async.commit_group;");
}
template <int N>
__device__ __forceinline__ void cp_wait() {
    asm volatile("cp.async.wait_group %0;" :: "n"(N));
}

// ---------------------------------------------------------------------------
// Prep 1: X fp32 -> fp16
// ---------------------------------------------------------------------------
__global__ __launch_bounds__(256) void prep_x_kernel(const float* __restrict__ x) {
    size_t i = ((size_t)blockIdx.x * 256 + threadIdx.x) * 8;
    float4 v0 = *reinterpret_cast<const float4*>(x + i);
    float4 v1 = *reinterpret_cast<const float4*>(x + i + 4);
    __half2 h0 = __floats2half2_rn(v0.x, v0.y);
    __half2 h1 = __floats2half2_rn(v0.z, v0.w);
    __half2 h2 = __floats2half2_rn(v1.x, v1.y);
    __half2 h3 = __floats2half2_rn(v1.z, v1.w);
    uint4 o;
    o.x = *(uint32_t*)&h0; o.y = *(uint32_t*)&h1;
    o.z = *(uint32_t*)&h2; o.w = *(uint32_t*)&h3;
    *reinterpret_cast<uint4*>(g_Xh + i) = o;
}

// ---------------------------------------------------------------------------
// Prep 2: weights -> fp16, transposed to [n][k]. z=0 -> g_Bt, z=1 -> g_Br.
// ---------------------------------------------------------------------------
__global__ __launch_bounds__(256) void prep_w_kernel(
    const float* __restrict__ wW,    // [2048,2048]
    const float* __restrict__ wxW,   // [1024,1024]
    const float* __restrict__ whW)   // [1024,1024]
{
    __shared__ float tile[32][33];
    const int n0 = blockIdx.x * 32, k0 = blockIdx.y * 32;
    const int which = blockIdx.z;
    const int tx = threadIdx.x, ty = threadIdx.y;   // 32 x 8

    for (int i = ty; i < 32; i += 8) {
        int k = k0 + i, n = n0 + tx;
        float v;
        if (which == 0) v = (n < 2048) ? wW[(size_t)k * 2048 + n]
                                       : wxW[(size_t)k * 1024 + (n - 2048)];
        else            v = (n < 2048) ? wW[(size_t)(1024 + k) * 2048 + n]
                                       : whW[(size_t)k * 1024 + (n - 2048)];
        tile[i][tx] = v;
    }
    __syncthreads();
    __half* dst = which ? g_Br : g_Bt;
    for (int i = ty; i < 32; i += 8) {
        int n = n0 + i, k = k0 + tx;
        dst[(size_t)n * 1024 + k] = __float2half_rn(tile[tx][i]);
    }
}

// ---------------------------------------------------------------------------
// Init: h0 -> fp16 ping buffer 0, reset grid-barrier counter.
// ---------------------------------------------------------------------------
__global__ void initB_kernel(const float* __restrict__ h0) {
    int i = blockIdx.x * 256 + threadIdx.x;   // 65536 threads
    g_h[i] = __float2half_rn(h0[i]);
    if (i == 0) g_arrive = 0;
}

// ---------------------------------------------------------------------------
// Phase A: C[32768,3072] = Xh @ Bt^T + bias, fp16 HMMA.
// Block tile 128x128, k-step 32, 3-stage cp.async pipeline (dynamic smem).
// 8 warps: wm = warp>>2 (2 m-halves of 64), wn = warp&3 (4 n-strips of 32).
// ---------------------------------------------------------------------------
#define PA_STRIDE_W 20            // 32-bit words per smem row
#define PA_STAGE_HALVES (2 * 128 * PA_STRIDE_W * 2)   // A + B per stage (10240)

__global__ __launch_bounds__(256) void phaseA_kernel(
    const float* __restrict__ wb,    // [2048]
    const float* __restrict__ wxb)   // [1024]
{
    extern __shared__ __align__(16) __half paSmem[];

    const int tid  = threadIdx.x;
    const int warp = tid >> 5, lane = tid & 31;
    const int gID  = lane >> 2, tig = lane & 3;
    const int wm   = warp >> 2, wn = warp & 3;
    const int row0 = blockIdx.y * 128;
    const int j0   = blockIdx.x * 128;

    const int lr0 = tid >> 1, lc0 = (tid & 1) << 1;  // loader rows / chunk pairs

    auto load_tile = [&](int buf, int kt) {
        __half* Ah = paSmem + buf * PA_STAGE_HALVES;
        __half* Bh = Ah + 128 * PA_STRIDE_W * 2;
#pragma unroll
        for (int cc = 0; cc < 2; cc++) {
            int c = lc0 + cc;
            cp_async16(&Ah[lr0 * (PA_STRIDE_W * 2) + c * 8],
                       g_Xh + (size_t)(row0 + lr0) * 1024 + kt + c * 8);
            cp_async16(&Bh[lr0 * (PA_STRIDE_W * 2) + c * 8],
                       g_Bt + (size_t)(j0 + lr0) * 1024 + kt + c * 8);
        }
    };

    float acc[4][4][4];
#pragma unroll
    for (int mi = 0; mi < 4; mi++)
#pragma unroll
        for (int ni = 0; ni < 4; ni++)
#pragma unroll
            for (int i = 0; i < 4; i++) acc[mi][ni][i] = 0.f;

    load_tile(0, 0);  cp_commit();
    load_tile(1, 32); cp_commit();

    const int m_base = wm * 64;
    const int n_base = wn * 32;

    for (int it = 0; it < 32; it++) {
        int buf = it % 3;
        if (it + 2 < 32) load_tile((it + 2) % 3, (it + 2) * 32);
        cp_commit();            // empty at tail keeps in-order accounting
        cp_wait<2>();           // tile `it` guaranteed complete
        __syncthreads();

        const uint32_t* Aw = reinterpret_cast<const uint32_t*>(
            paSmem + buf * PA_STAGE_HALVES);
        const uint32_t* Bw = Aw + 128 * PA_STRIDE_W;

#pragma unroll
        for (int ki = 0; ki < 2; ki++) {
            int wbase = ki * 8;
            uint32_t a[4][4];
#pragma unroll
            for (int mi = 0; mi < 4; mi++) {
                int r = m_base + mi * 16 + gID;
                a[mi][0] = Aw[r * PA_STRIDE_W + wbase + tig];
                a[mi][1] = Aw[(r + 8) * PA_STRIDE_W + wbase + tig];
                a[mi][2] = Aw[r * PA_STRIDE_W + wbase + tig + 4];
                a[mi][3] = Aw[(r + 8) * PA_STRIDE_W + wbase + tig + 4];
            }
#pragma unroll
            for (int ni = 0; ni < 4; ni++) {
                int n = n_base + ni * 8 + gID;
                uint32_t b0 = Bw[n * PA_STRIDE_W + wbase + tig];
                uint32_t b1 = Bw[n * PA_STRIDE_W + wbase + tig + 4];
#pragma unroll
                for (int mi = 0; mi < 4; mi++)
                    mma_f16(acc[mi][ni], a[mi][0], a[mi][1], a[mi][2], a[mi][3], b0, b1);
            }
        }
        __syncthreads();
    }

    // epilogue: bias + permuted fp32 store to g_XG ([t][b] row order)
    float bv[4][2];
#pragma unroll
    for (int ni = 0; ni < 4; ni++) {
        int col = j0 + n_base + ni * 8 + tig * 2;
        if (col < 2048) { bv[ni][0] = wb[col];         bv[ni][1] = wb[col + 1]; }
        else            { bv[ni][0] = wxb[col - 2048]; bv[ni][1] = wxb[col - 2047]; }
    }
#pragma unroll
    for (int mi = 0; mi < 4; mi++) {
#pragma unroll
        for (int h = 0; h < 2; h++) {
            int grow = row0 + m_base + mi * 16 + gID + h * 8;  // (b*512 + t)
            int bb = grow >> 9, tt = grow & 511;
            size_t orow = (size_t)(tt * 64 + bb) * 3072;
#pragma unroll
            for (int ni = 0; ni < 4; ni++) {
                int col = j0 + n_base + ni * 8 + tig * 2;
                g_XG[orow + col]     = acc[mi][ni][h * 2]     + bv[ni][0];
                g_XG[orow + col + 1] = acc[mi][ni][h * 2 + 1] + bv[ni][1];
            }
        }
    }
}

// ---------------------------------------------------------------------------
// Phase B: persistent kernel. 128 blocks x 128 threads (4 warps), co-resident.
// Block = 8-column tile of latent dim; weights cached in smem fp16.
// Warps are K-SPLIT: warp w accumulates k in [256w, 256w+256) for ALL 64 rows
// and all 3 groups (no fragment duplication), then partials are reduced via a
// smem buffer overlaid on the (dead) h-staging area. h_prev for the epilogue
// is carried in registers across steps; XG for t+1 prefetched before the
// grid barrier.
// ---------------------------------------------------------------------------
#define SMEM_W_STRIDE 1032   // halves per weight column (conflict-free)
#define SMEM_H_STRIDE 1032   // halves per h row

__global__ __launch_bounds__(128) void phaseB_kernel(
    const float* __restrict__ h0,
    const float* __restrict__ whb,    // [1024]
    float* __restrict__ out)          // [64,512,1024]
{
    extern __shared__ __align__(16) __half smem[];
    __half* Wt = smem;                               // [3*8][1032]
    __half* Hs = smem + 3 * 8 * SMEM_W_STRIDE;       // [64][1032]  (Red overlays)

    const int tid  = threadIdx.x;
    const int warp = tid >> 5, lane = tid & 31;
    const int gID  = lane >> 2, tig = lane & 3;
    const int jt   = blockIdx.x * 8;
    const int jcol0 = jt + tig * 2;
    const int kw0  = warp * 128;                     // word offset of warp's k-slice

    // one-time: weights from g_Br (already [n][k] fp16) -> smem, 16B copies
    for (int idx = tid; idx < 3 * 8 * 128; idx += 128) {
        int row = idx >> 7, c = idx & 127;           // row = g*8+col
        int g = row >> 3, col = row & 7;
        uint4 v = *reinterpret_cast<const uint4*>(
            g_Br + (size_t)(g * 1024 + jt + col) * 1024 + c * 8);
        *reinterpret_cast<uint4*>(Wt + (size_t)row * SMEM_W_STRIDE + c * 8) = v;
    }
    const float bwh0 = whb[jcol0];
    const float bwh1 = whb[jcol0 + 1];

    // register-carried h_prev for this thread's 4 output slots (r = warp*16+gID+h*8)
    float hpv[2][2];
#pragma unroll
    for (int h = 0; h < 2; h++) {
        int r = warp * 16 + gID + h * 8;
        hpv[h][0] = h0[(size_t)r * 1024 + jcol0];
        hpv[h][1] = h0[(size_t)r * 1024 + jcol0 + 1];
    }
    // prefetch XG for t=0
    float xg[2][2][3];
#pragma unroll
    for (int h = 0; h < 2; h++) {
        int r = warp * 16 + gID + h * 8;
        const float* xr = g_XG + (size_t)r * 3072 + jcol0;
#pragma unroll
        for (int cc = 0; cc < 2; cc++) {
            xg[h][cc][0] = xr[cc];
            xg[h][cc][1] = xr[1024 + cc];
            xg[h][cc][2] = xr[2048 + cc];
        }
    }
    __syncthreads();

    float* Red = reinterpret_cast<float*>(Hs);       // [src4][mt4][g3][lane32][4]

    for (int t = 0; t < 512; t++) {
        const __half* hsrc = g_h + (size_t)(t & 1) * 65536;
        __half*       hdst = g_h + (size_t)((t + 1) & 1) * 65536;

        // ---- stage h (fp16) into smem via cp.async (L1-bypass)
#pragma unroll 4
        for (int i = tid; i < 8192; i += 128) {
            int r = i >> 7, c = i & 127;
            cp_async16(Hs + (size_t)r * SMEM_H_STRIDE + c * 8,
                       hsrc + (size_t)r * 1024 + c * 8);
        }
        cp_commit();
        cp_wait<0>();
        __syncthreads();

        // ---- k-slice MMA: all 4 m-tiles, 3 groups, k in [kw0*2, kw0*2+256)
        float acc[4][3][4];
#pragma unroll
        for (int mt = 0; mt < 4; mt++)
#pragma unroll
            for (int g = 0; g < 3; g++)
#pragma unroll
                for (int i = 0; i < 4; i++) acc[mt][g][i] = 0.f;

        const uint32_t* Aw = reinterpret_cast<const uint32_t*>(Hs);
        const uint32_t* Bw = reinterpret_cast<const uint32_t*>(Wt);

#pragma unroll 4
        for (int kk = 0; kk < 16; kk++) {
            int kw = kw0 + kk * 8;
            uint32_t a[4][4];
#pragma unroll
            for (int mt = 0; mt < 4; mt++) {
                int r = mt * 16 + gID;
                a[mt][0] = Aw[r * (SMEM_H_STRIDE / 2) + kw + tig];
                a[mt][1] = Aw[(r + 8) * (SMEM_H_STRIDE / 2) + kw + tig];
                a[mt][2] = Aw[r * (SMEM_H_STRIDE / 2) + kw + tig + 4];
                a[mt][3] = Aw[(r + 8) * (SMEM_H_STRIDE / 2) + kw + tig + 4];
            }
#pragma unroll
            for (int g = 0; g < 3; g++) {
                uint32_t b0 = Bw[(g * 8 + gID) * (SMEM_W_STRIDE / 2) + kw + tig];
                uint32_t b1 = Bw[(g * 8 + gID) * (SMEM_W_STRIDE / 2) + kw + tig + 4];
#pragma unroll
                for (int mt = 0; mt < 4; mt++)
                    mma_f16(acc[mt][g], a[mt][0], a[mt][1], a[mt][2], a[mt][3], b0, b1);
            }
        }
        __syncthreads();   // Hs reads done before Red overlays it

        // ---- write partial sums (all mt) to smem
#pragma unroll
        for (int mt = 0; mt < 4; mt++)
#pragma unroll
            for (int g = 0; g < 3; g++) {
                int idx = (((warp * 4 + mt) * 3 + g) * 32 + lane) * 4;
                *reinterpret_cast<float4*>(Red + idx) =
                    make_float4(acc[mt][g][0], acc[mt][g][1], acc[mt][g][2], acc[mt][g][3]);
            }
        __syncthreads();

        // ---- reduce: this warp owns m-tile = warp (rows warp*16..warp*16+15)
        float facc[3][4];
#pragma unroll
        for (int g = 0; g < 3; g++)
#pragma unroll
            for (int c = 0; c < 4; c++) facc[g][c] = 0.f;
#pragma unroll
        for (int src = 0; src < 4; src++)
#pragma unroll
            for (int g = 0; g < 3; g++) {
                float4 v = *reinterpret_cast<const float4*>(
                    Red + (((src * 4 + warp) * 3 + g) * 32 + lane) * 4);
                facc[g][0] += v.x; facc[g][1] += v.y;
                facc[g][2] += v.z; facc[g][3] += v.w;
            }

        // ---- fused nonlinearity + stores
#pragma unroll
        for (int h = 0; h < 2; h++) {
            int r = warp * 16 + gID + h * 8;
            float hn[2];
#pragma unroll
            for (int cc = 0; cc < 2; cc++) {
                float g1 = facc[0][h * 2 + cc] + xg[h][cc][0];
                float g2 = facc[1][h * 2 + cc] + xg[h][cc][1];
                float hm = facc[2][h * 2 + cc] + ((cc == 0) ? bwh0 : bwh1);
                float xm = xg[h][cc][2];
                float hs = 1.f / (1.f + __expf(-g1));
                float os = 1.f / (1.f + __expf(-g2));
                float mm = xm + hs * hm;
                hn[cc] = os * hpv[h][cc] + (1.f - os) * tanhf(mm);
                out[((size_t)r * 512 + t) * 1024 + jcol0 + cc] = hn[cc];
                hpv[h][cc] = hn[cc];             // register-carry for next step
            }
            *(reinterpret_cast<__half2*>(hdst + (size_t)r * 1024 + jcol0)) =
                __floats2half2_rn(hn[0], hn[1]);
        }

        // ---- prefetch XG for t+1 (independent of barrier; hides DRAM latency)
        if (t + 1 < 512) {
            size_t xb = (size_t)(t + 1) * 64 * 3072;
#pragma unroll
            for (int h = 0; h < 2; h++) {
                int r = warp * 16 + gID + h * 8;
                const float* xr = g_XG + xb + (size_t)r * 3072 + jcol0;
#pragma unroll
                for (int cc = 0; cc < 2; cc++) {
                    xg[h][cc][0] = xr[cc];
                    xg[h][cc][1] = xr[1024 + cc];
                    xg[h][cc][2] = xr[2048 + cc];
                }
            }
        }

        // ---- grid barrier (release h writes, wait for all 128 blocks)
        __threadfence();
        __syncthreads();
        if (tid == 0) {
            atomicAdd(&g_arrive, 1u);
            unsigned target = (unsigned)(t + 1) * 128u;
            unsigned v;
            do {
                asm volatile("ld.global.acquire.gpu.u32 %0, [%1];"
                             : "=r"(v) : "l"(&g_arrive));
            } while (v < target);
        }
        __syncthreads();
    }
}

extern "C" void kernel_launch(void* const* d_in, const int* in_sizes, int n_in,
                              void* d_out, int out_size) {
    const float* x   = (const float*)d_in[0];
    const float* h0  = (const float*)d_in[1];
    const float* wW  = (const float*)d_in[2];
    const float* wb  = (const float*)d_in[3];
    const float* wxW = (const float*)d_in[4];
    const float* wxb = (const float*)d_in[5];
    const float* whW = (const float*)d_in[6];
    const float* whb = (const float*)d_in[7];
    float* out = (float*)d_out;

    const int smemA = 3 * PA_STAGE_HALVES * (int)sizeof(__half);     // ~60 KB
    const int smemB = (3 * 8 * SMEM_W_STRIDE + 64 * SMEM_H_STRIDE) * (int)sizeof(__half);
    cudaFuncSetAttribute(phaseA_kernel,
                         cudaFuncAttributeMaxDynamicSharedMemorySize, smemA);
    cudaFuncSetAttribute(phaseB_kernel,
                         cudaFuncAttributeMaxDynamicSharedMemorySize, smemB);

    prep_x_kernel<<<16384, 256>>>(x);
    prep_w_kernel<<<dim3(96, 32, 2), dim3(32, 8)>>>(wW, wxW, whW);
    initB_kernel<<<256, 256>>>(h0);
    phaseA_kernel<<<dim3(24, 256), 256, smemA>>>(wb, wxb);
    phaseB_kernel<<<128, 128, smemB>>>(h0, whb, out);
}

// round 7
// speedup vs baseline: 5.4345x; 1.1459x over previous
#include <cuda_runtime.h>
#include <cuda_fp16.h>
#include <cstdint>

// GruLayer: B=64, T=512, D_in=L=1024.
// Prep: X -> fp16 g_Xh; weights -> fp16 transposed g_Bt (x-proj) / g_Br (recurrent).
// Phase A (fp16 HMMA, 128x256 tile, ldmatrix, 3-stage cp.async):
//   XG = x @ [w_W_top | wx_W] + bias
// Phase B (persistent, 512 steps, fp16 HMMA, k-split warps, chunked per-warp
//   h staging): G = h_{t-1} @ [w_W_bot | wh_W]; hs=sig(G1+XG1); os=sig(G2+XG2)
//   h_t = os*h + (1-os)*tanh(XGm + hs*(Gm + wh_b))

__device__ float  g_XG[(size_t)32768 * 3072];   // [t*64+b][3072] scratch (~403 MB)
__device__ __half g_Xh[(size_t)32768 * 1024];   // X fp16 (64 MB)
__device__ __half g_Bt[(size_t)3072 * 1024];    // [n][k] fp16 x-proj weights
__device__ __half g_Br[(size_t)3072 * 1024];    // [n][k] fp16 recurrent weights
__device__ __half g_h[2 * 64 * 1024];           // fp16 h ping-pong
__device__ unsigned g_arrive;                   // grid barrier counter

__device__ __forceinline__ void mma_f16(float* c,
                                        uint32_t a0, uint32_t a1, uint32_t a2, uint32_t a3,
                                        uint32_t b0, uint32_t b1) {
    asm volatile(
        "mma.sync.aligned.m16n8k16.row.col.f32.f16.f16.f32 "
        "{%0,%1,%2,%3},{%4,%5,%6,%7},{%8,%9},{%0,%1,%2,%3};"
        : "+f"(c[0]), "+f"(c[1]), "+f"(c[2]), "+f"(c[3])
        : "r"(a0), "r"(a1), "r"(a2), "r"(a3), "r"(b0), "r"(b1));
}

__device__ __forceinline__ void ldsm_x4(uint32_t& r0, uint32_t& r1,
                                        uint32_t& r2, uint32_t& r3,
                                        const void* p) {
    uint32_t a = (uint32_t)__cvta_generic_to_shared(p);
    asm volatile("ldmatrix.sync.aligned.m8n8.x4.shared.b16 {%0,%1,%2,%3}, [%4];"
                 : "=r"(r0), "=r"(r1), "=r"(r2), "=r"(r3) : "r"(a));
}

__device__ __forceinline__ void cp_async16(void* smem, const void* gmem) {
    uint32_t s = (uint32_t)__cvta_generic_to_shared(smem);
    asm volatile("cp.async.cg.shared.global [%0], [%1], 16;" :: "r"(s), "l"(gmem));
}
__device__ __forceinline__ void cp_commit() {
    asm volatile("cp.async.commit_group;");
}
template <int N>
__device__ __forceinline__ void cp_wait() {
    asm volatile("cp.async.wait_group %0;" :: "n"(N));
}

// ---------------------------------------------------------------------------
// Prep 1: X fp32 -> fp16
// ---------------------------------------------------------------------------
__global__ __launch_bounds__(256) void prep_x_kernel(const float* __restrict__ x) {
    size_t i = ((size_t)blockIdx.x * 256 + threadIdx.x) * 8;
    float4 v0 = *reinterpret_cast<const float4*>(x + i);
    float4 v1 = *reinterpret_cast<const float4*>(x + i + 4);
    __half2 h0 = __floats2half2_rn(v0.x, v0.y);
    __half2 h1 = __floats2half2_rn(v0.z, v0.w);
    __half2 h2 = __floats2half2_rn(v1.x, v1.y);
    __half2 h3 = __floats2half2_rn(v1.z, v1.w);
    uint4 o;
    o.x = *(uint32_t*)&h0; o.y = *(uint32_t*)&h1;
    o.z = *(uint32_t*)&h2; o.w = *(uint32_t*)&h3;
    *reinterpret_cast<uint4*>(g_Xh + i) = o;
}

// ---------------------------------------------------------------------------
// Prep 2: weights -> fp16, transposed to [n][k]. z=0 -> g_Bt, z=1 -> g_Br.
// ---------------------------------------------------------------------------
__global__ __launch_bounds__(256) void prep_w_kernel(
    const float* __restrict__ wW,    // [2048,2048]
    const float* __restrict__ wxW,   // [1024,1024]
    const float* __restrict__ whW)   // [1024,1024]
{
    __shared__ float tile[32][33];
    const int n0 = blockIdx.x * 32, k0 = blockIdx.y * 32;
    const int which = blockIdx.z;
    const int tx = threadIdx.x, ty = threadIdx.y;   // 32 x 8

    for (int i = ty; i < 32; i += 8) {
        int k = k0 + i, n = n0 + tx;
        float v;
        if (which == 0) v = (n < 2048) ? wW[(size_t)k * 2048 + n]
                                       : wxW[(size_t)k * 1024 + (n - 2048)];
        else            v = (n < 2048) ? wW[(size_t)(1024 + k) * 2048 + n]
                                       : whW[(size_t)k * 1024 + (n - 2048)];
        tile[i][tx] = v;
    }
    __syncthreads();
    __half* dst = which ? g_Br : g_Bt;
    for (int i = ty; i < 32; i += 8) {
        int n = n0 + i, k = k0 + tx;
        dst[(size_t)n * 1024 + k] = __float2half_rn(tile[tx][i]);
    }
}

// ---------------------------------------------------------------------------
// Init: h0 -> fp16 ping buffer 0, reset grid-barrier counter.
// ---------------------------------------------------------------------------
__global__ void initB_kernel(const float* __restrict__ h0) {
    int i = blockIdx.x * 256 + threadIdx.x;   // 65536 threads
    g_h[i] = __float2half_rn(h0[i]);
    if (i == 0) g_arrive = 0;
}

// ---------------------------------------------------------------------------
// Phase A: C[32768,3072] = Xh @ Bt^T + bias, fp16 HMMA + ldmatrix.
// Block tile 128m x 256n, 512 threads (16 warps, warp tile 32x64), k-step 32,
// 3-stage cp.async pipeline. Smem row stride 40 halves -> conflict-free LDSM.
// ---------------------------------------------------------------------------
#define PA2_ST 40                       // halves per smem row
#define PA2_A_HALVES (128 * PA2_ST)     // 5120
#define PA2_STAGE (384 * PA2_ST)        // 15360 halves per stage (A + B)

__global__ __launch_bounds__(512, 1) void phaseA_kernel(
    const float* __restrict__ wb,    // [2048]
    const float* __restrict__ wxb)   // [1024]
{
    extern __shared__ __align__(16) __half paSmem[];

    const int tid  = threadIdx.x;
    const int warp = tid >> 5, lane = tid & 31;
    const int gID  = lane >> 2, tig = lane & 3;
    const int wm   = warp & 3, wn = warp >> 2;     // 4m x 4n warp grid
    const int row0 = blockIdx.y * 128;
    const int j0   = blockIdx.x * 256;

    // ldmatrix per-lane row/k offsets
    const int a_row  = lane & 15;
    const int a_koff = (lane >> 4) << 3;
    const int b_row  = (lane & 7) | ((lane >> 4) << 3);
    const int b_koff = ((lane >> 3) & 1) << 3;

    auto load_tile = [&](int buf, int kt) {
        __half* Ah = paSmem + buf * PA2_STAGE;
        __half* Bh = Ah + PA2_A_HALVES;
#pragma unroll
        for (int i = tid; i < 1536; i += 512) {
            int row = i >> 2, c = i & 3;           // 16B chunk index
            if (row < 128)
                cp_async16(Ah + row * PA2_ST + c * 8,
                           g_Xh + (size_t)(row0 + row) * 1024 + kt + c * 8);
            else
                cp_async16(Bh + (row - 128) * PA2_ST + c * 8,
                           g_Bt + (size_t)(j0 + row - 128) * 1024 + kt + c * 8);
        }
    };

    float acc[2][8][4];
#pragma unroll
    for (int mi = 0; mi < 2; mi++)
#pragma unroll
        for (int ni = 0; ni < 8; ni++)
#pragma unroll
            for (int i = 0; i < 4; i++) acc[mi][ni][i] = 0.f;

    load_tile(0, 0);  cp_commit();
    load_tile(1, 32); cp_commit();

    for (int it = 0; it < 32; it++) {
        int buf = it % 3;
        if (it + 2 < 32) load_tile((it + 2) % 3, (it + 2) * 32);
        cp_commit();
        cp_wait<2>();
        __syncthreads();

        const __half* Ah = paSmem + buf * PA2_STAGE;
        const __half* Bh = Ah + PA2_A_HALVES;

#pragma unroll
        for (int ki = 0; ki < 2; ki++) {
            int kb = ki * 16;
            uint32_t a[2][4];
#pragma unroll
            for (int mi = 0; mi < 2; mi++)
                ldsm_x4(a[mi][0], a[mi][1], a[mi][2], a[mi][3],
                        Ah + (wm * 32 + mi * 16 + a_row) * PA2_ST + kb + a_koff);
#pragma unroll
            for (int nj = 0; nj < 4; nj++) {
                uint32_t r0, r1, r2, r3;
                ldsm_x4(r0, r1, r2, r3,
                        Bh + (wn * 64 + nj * 16 + b_row) * PA2_ST + kb + b_koff);
#pragma unroll
                for (int mi = 0; mi < 2; mi++) {
                    mma_f16(acc[mi][nj * 2],     a[mi][0], a[mi][1], a[mi][2], a[mi][3], r0, r1);
                    mma_f16(acc[mi][nj * 2 + 1], a[mi][0], a[mi][1], a[mi][2], a[mi][3], r2, r3);
                }
            }
        }
        __syncthreads();
    }

    // epilogue: bias + permuted fp32 store to g_XG ([t][b] row order)
    float bv[8][2];
#pragma unroll
    for (int ni = 0; ni < 8; ni++) {
        int col = j0 + wn * 64 + ni * 8 + tig * 2;
        if (col < 2048) { bv[ni][0] = wb[col];         bv[ni][1] = wb[col + 1]; }
        else            { bv[ni][0] = wxb[col - 2048]; bv[ni][1] = wxb[col - 2047]; }
    }
#pragma unroll
    for (int mi = 0; mi < 2; mi++) {
#pragma unroll
        for (int h = 0; h < 2; h++) {
            int grow = row0 + wm * 32 + mi * 16 + gID + h * 8;  // (b*512 + t)
            int bb = grow >> 9, tt = grow & 511;
            size_t orow = (size_t)(tt * 64 + bb) * 3072;
#pragma unroll
            for (int ni = 0; ni < 8; ni++) {
                int col = j0 + wn * 64 + ni * 8 + tig * 2;
                g_XG[orow + col]     = acc[mi][ni][h * 2]     + bv[ni][0];
                g_XG[orow + col + 1] = acc[mi][ni][h * 2 + 1] + bv[ni][1];
            }
        }
    }
}

// ---------------------------------------------------------------------------
// Phase B: persistent kernel. 128 blocks x 128 threads (4 warps), co-resident.
// Block = 8-column tile of latent dim; weights cached in smem fp16.
// Warps are K-SPLIT (warp w owns k in [256w,256w+256) for all 64 rows, all 3
// groups). h staging is PER-WARP and CHUNKED: each warp cp.asyncs only its own
// k-slice in 4 groups of 8KB and starts MMA as soon as group 0 lands (no
// block-wide sync before MMA). Partials reduced via smem overlay; h_prev
// register-carried; XG for t+1 prefetched before the grid barrier.
// ---------------------------------------------------------------------------
#define SMEM_W_STRIDE 1032   // halves per weight column (conflict-free)
#define SMEM_H_STRIDE 1032   // halves per h row

__global__ __launch_bounds__(128) void phaseB_kernel(
    const float* __restrict__ h0,
    const float* __restrict__ whb,    // [1024]
    float* __restrict__ out)          // [64,512,1024]
{
    extern __shared__ __align__(16) __half smem[];
    __half* Wt = smem;                               // [3*8][1032]
    __half* Hs = smem + 3 * 8 * SMEM_W_STRIDE;       // [64][1032]  (Red overlays)

    const int tid  = threadIdx.x;
    const int warp = tid >> 5, lane = tid & 31;
    const int gID  = lane >> 2, tig = lane & 3;
    const int jt   = blockIdx.x * 8;
    const int jcol0 = jt + tig * 2;
    const int kw0  = warp * 128;                     // word offset of warp's k-slice
    const int kh0  = warp * 256;                     // half offset of warp's k-slice

    // one-time: weights from g_Br (already [n][k] fp16) -> smem, 16B copies
    for (int idx = tid; idx < 3 * 8 * 128; idx += 128) {
        int row = idx >> 7, c = idx & 127;           // row = g*8+col
        int g = row >> 3, col = row & 7;
        uint4 v = *reinterpret_cast<const uint4*>(
            g_Br + (size_t)(g * 1024 + jt + col) * 1024 + c * 8);
        *reinterpret_cast<uint4*>(Wt + (size_t)row * SMEM_W_STRIDE + c * 8) = v;
    }
    const float bwh0 = whb[jcol0];
    const float bwh1 = whb[jcol0 + 1];

    // register-carried h_prev for this thread's 4 output slots
    float hpv[2][2];
#pragma unroll
    for (int h = 0; h < 2; h++) {
        int r = warp * 16 + gID + h * 8;
        hpv[h][0] = h0[(size_t)r * 1024 + jcol0];
        hpv[h][1] = h0[(size_t)r * 1024 + jcol0 + 1];
    }
    // prefetch XG for t=0
    float xg[2][2][3];
#pragma unroll
    for (int h = 0; h < 2; h++) {
        int r = warp * 16 + gID + h * 8;
        const float* xr = g_XG + (size_t)r * 3072 + jcol0;
#pragma unroll
        for (int cc = 0; cc < 2; cc++) {
            xg[h][cc][0] = xr[cc];
            xg[h][cc][1] = xr[1024 + cc];
            xg[h][cc][2] = xr[2048 + cc];
        }
    }
    __syncthreads();

    float* Red = reinterpret_cast<float*>(Hs);       // [src4][mt4][g3][lane32][4]

    for (int t = 0; t < 512; t++) {
        const __half* hsrc = g_h + (size_t)(t & 1) * 65536;
        __half*       hdst = g_h + (size_t)((t + 1) & 1) * 65536;

        // ---- per-warp chunked h staging: 4 groups of (64 rows x 64 halves)
#pragma unroll
        for (int q = 0; q < 4; q++) {
#pragma unroll
            for (int i = lane; i < 512; i += 32) {
                int r = i >> 3, cc = i & 7;
                cp_async16(Hs + (size_t)r * SMEM_H_STRIDE + kh0 + q * 64 + cc * 8,
                           hsrc + (size_t)r * 1024 + kh0 + q * 64 + cc * 8);
            }
            cp_commit();
        }

        // ---- k-slice MMA, overlapped with remaining staging groups
        float acc[4][3][4];
#pragma unroll
        for (int mt = 0; mt < 4; mt++)
#pragma unroll
            for (int g = 0; g < 3; g++)
#pragma unroll
                for (int i = 0; i < 4; i++) acc[mt][g][i] = 0.f;

        const uint32_t* Aw = reinterpret_cast<const uint32_t*>(Hs);
        const uint32_t* Bw = reinterpret_cast<const uint32_t*>(Wt);

        auto do4 = [&](int q) {
#pragma unroll
            for (int kk2 = 0; kk2 < 4; kk2++) {
                int kw = kw0 + (q * 4 + kk2) * 8;
                uint32_t a[4][4];
#pragma unroll
                for (int mt = 0; mt < 4; mt++) {
                    int r = mt * 16 + gID;
                    a[mt][0] = Aw[r * (SMEM_H_STRIDE / 2) + kw + tig];
                    a[mt][1] = Aw[(r + 8) * (SMEM_H_STRIDE / 2) + kw + tig];
                    a[mt][2] = Aw[r * (SMEM_H_STRIDE / 2) + kw + tig + 4];
                    a[mt][3] = Aw[(r + 8) * (SMEM_H_STRIDE / 2) + kw + tig + 4];
                }
#pragma unroll
                for (int g = 0; g < 3; g++) {
                    uint32_t b0 = Bw[(g * 8 + gID) * (SMEM_W_STRIDE / 2) + kw + tig];
                    uint32_t b1 = Bw[(g * 8 + gID) * (SMEM_W_STRIDE / 2) + kw + tig + 4];
#pragma unroll
                    for (int mt = 0; mt < 4; mt++)
                        mma_f16(acc[mt][g], a[mt][0], a[mt][1], a[mt][2], a[mt][3], b0, b1);
                }
            }
        };
        cp_wait<3>(); do4(0);
        cp_wait<2>(); do4(1);
        cp_wait<1>(); do4(2);
        cp_wait<0>(); do4(3);
        __syncthreads();   // all warps done with Hs before Red overlays it

        // ---- write partial sums to smem
#pragma unroll
        for (int mt = 0; mt < 4; mt++)
#pragma unroll
            for (int g = 0; g < 3; g++) {
                int idx = (((warp * 4 + mt) * 3 + g) * 32 + lane) * 4;
                *reinterpret_cast<float4*>(Red + idx) =
                    make_float4(acc[mt][g][0], acc[mt][g][1], acc[mt][g][2], acc[mt][g][3]);
            }
        __syncthreads();

        // ---- reduce: warp owns m-tile = warp
        float facc[3][4];
#pragma unroll
        for (int g = 0; g < 3; g++)
#pragma unroll
            for (int c = 0; c < 4; c++) facc[g][c] = 0.f;
#pragma unroll
        for (int src = 0; src < 4; src++)
#pragma unroll
            for (int g = 0; g < 3; g++) {
                float4 v = *reinterpret_cast<const float4*>(
                    Red + (((src * 4 + warp) * 3 + g) * 32 + lane) * 4);
                facc[g][0] += v.x; facc[g][1] += v.y;
                facc[g][2] += v.z; facc[g][3] += v.w;
            }

        // ---- fused nonlinearity + stores
#pragma unroll
        for (int h = 0; h < 2; h++) {
            int r = warp * 16 + gID + h * 8;
            float hn[2];
#pragma unroll
            for (int cc = 0; cc < 2; cc++) {
                float g1 = facc[0][h * 2 + cc] + xg[h][cc][0];
                float g2 = facc[1][h * 2 + cc] + xg[h][cc][1];
                float hm = facc[2][h * 2 + cc] + ((cc == 0) ? bwh0 : bwh1);
                float xm = xg[h][cc][2];
                float hs = 1.f / (1.f + __expf(-g1));
                float os = 1.f / (1.f + __expf(-g2));
                float mm = xm + hs * hm;
                hn[cc] = os * hpv[h][cc] + (1.f - os) * tanhf(mm);
                out[((size_t)r * 512 + t) * 1024 + jcol0 + cc] = hn[cc];
                hpv[h][cc] = hn[cc];             // register-carry for next step
            }
            *(reinterpret_cast<__half2*>(hdst + (size_t)r * 1024 + jcol0)) =
                __floats2half2_rn(hn[0], hn[1]);
        }

        // ---- prefetch XG for t+1 (hides DRAM latency behind the barrier)
        if (t + 1 < 512) {
            size_t xb = (size_t)(t + 1) * 64 * 3072;
#pragma unroll
            for (int h = 0; h < 2; h++) {
                int r = warp * 16 + gID + h * 8;
                const float* xr = g_XG + xb + (size_t)r * 3072 + jcol0;
#pragma unroll
                for (int cc = 0; cc < 2; cc++) {
                    xg[h][cc][0] = xr[cc];
                    xg[h][cc][1] = xr[1024 + cc];
                    xg[h][cc][2] = xr[2048 + cc];
                }
            }
        }

        // ---- grid barrier
        __threadfence();
        __syncthreads();
        if (tid == 0) {
            atomicAdd(&g_arrive, 1u);
            unsigned target = (unsigned)(t + 1) * 128u;
            unsigned v;
            do {
                asm volatile("ld.global.acquire.gpu.u32 %0, [%1];"
                             : "=r"(v) : "l"(&g_arrive));
            } while (v < target);
        }
        __syncthreads();
    }
}

extern "C" void kernel_launch(void* const* d_in, const int* in_sizes, int n_in,
                              void* d_out, int out_size) {
    const float* x   = (const float*)d_in[0];
    const float* h0  = (const float*)d_in[1];
    const float* wW  = (const float*)d_in[2];
    const float* wb  = (const float*)d_in[3];
    const float* wxW = (const float*)d_in[4];
    const float* wxb = (const float*)d_in[5];
    const float* whW = (const float*)d_in[6];
    const float* whb = (const float*)d_in[7];
    float* out = (float*)d_out;

    const int smemA = 3 * PA2_STAGE * (int)sizeof(__half);           // 92160 B
    const int smemB = (3 * 8 * SMEM_W_STRIDE + 64 * SMEM_H_STRIDE) * (int)sizeof(__half);
    cudaFuncSetAttribute(phaseA_kernel,
                         cudaFuncAttributeMaxDynamicSharedMemorySize, smemA);
    cudaFuncSetAttribute(phaseB_kernel,
                         cudaFuncAttributeMaxDynamicSharedMemorySize, smemB);

    prep_x_kernel<<<16384, 256>>>(x);
    prep_w_kernel<<<dim3(96, 32, 2), dim3(32, 8)>>>(wW, wxW, whW);
    initB_kernel<<<256, 256>>>(h0);
    phaseA_kernel<<<dim3(12, 256), 512, smemA>>>(wb, wxb);
    phaseB_kernel<<<128, 128, smemB>>>(h0, whb, out);
}